// round 3
// baseline (speedup 1.0000x reference)
#include <cuda_runtime.h>
#include <cstdint>

// Unpool (stride-2 zero insertion):
//   in : (B, C, 112, 112) fp32, contiguous
//   out: (B, C, 224, 224) fp32, out[..., ::2, ::2] = in, else 0
//
// One thread per (global input row, float4-of-input column):
//   - loads one float4 (4 input values) with DEFAULT caching (input ~103MB
//     nearly fits in 126MB L2 -> stays resident across graph replays),
//   - stores two float4 to the even output row: [x0,0,x1,0], [x2,0,x3,0],
//   - stores two zero float4 to the following odd output row.
// All accesses coalesced; stores use .cs (write-once, evict-first).

namespace {
constexpr int W4_IN  = 28;   // float4 per 112-wide input row
constexpr int W4_OUT = 56;   // float4 per 224-wide output row
}

__global__ void __launch_bounds__(256)
unpool_kernel(const float4* __restrict__ x4,
              float4* __restrict__ out,
              int total)              // total = global_input_rows * 28
{
    int idx = blockIdx.x * blockDim.x + threadIdx.x;
    if (idx >= total) return;

    int irow = idx / W4_IN;           // global input row (img*112 + ih)
    int c    = idx - irow * W4_IN;    // float4 column in input row

    // default caching: keep input resident in L2 across replays
    float4 a = __ldg(&x4[irow * W4_IN + c]);

    float4* even = out + (size_t)(2 * irow)     * W4_OUT + 2 * c;
    float4* odd  = out + (size_t)(2 * irow + 1) * W4_OUT + 2 * c;

    const float4 z = make_float4(0.f, 0.f, 0.f, 0.f);

    // streaming stores: write-once, evict-first
    __stcs(even + 0, make_float4(a.x, 0.f, a.y, 0.f));
    __stcs(even + 1, make_float4(a.z, 0.f, a.w, 0.f));
    __stcs(odd  + 0, z);
    __stcs(odd  + 1, z);
}

extern "C" void kernel_launch(void* const* d_in, const int* in_sizes, int n_in,
                              void* d_out, int out_size)
{
    const float4* x4 = (const float4*)d_in[0];
    float4* out = (float4*)d_out;

    // out_size = B*C*224*224 floats. Threads = input floats / 4 = out_size / 16.
    int total = out_size / 16;

    const int threads = 256;
    int blocks = (total + threads - 1) / threads;
    unpool_kernel<<<blocks, threads>>>(x4, out, total);
}

// round 4
// speedup vs baseline: 1.0092x; 1.0092x over previous
#include <cuda_runtime.h>
#include <cstdint>

// Unpool (stride-2 zero insertion):
//   in : (B, C, 112, 112) fp32, contiguous
//   out: (B, C, 224, 224) fp32, out[..., ::2, ::2] = in, else 0
//
// One thread per input float4 (4 values = 16B read):
//   - one 256-bit STG (.cs) to the even output row: [x0,0,x1,0,x2,0,x3,0]
//   - one 256-bit STG (.cs) of zeros to the following odd output row
// 2x fewer store instructions / L1 wavefronts than the 128-bit version
// (L1 was 75% busy and throttling the write stream).
// Both store addresses are 32B-aligned: offsets are (2*irow*56 + 2c)*16 bytes.

namespace {
constexpr int W4_IN  = 28;   // float4 per 112-wide input row
constexpr int W4_OUT = 56;   // float4 per 224-wide output row
}

__device__ __forceinline__ void stg256_cs(void* p,
                                          float v0, float v1, float v2, float v3,
                                          float v4, float v5, float v6, float v7)
{
    asm volatile(
        "st.global.cs.v8.f32 [%0], {%1,%2,%3,%4,%5,%6,%7,%8};"
        :: "l"(p),
           "f"(v0), "f"(v1), "f"(v2), "f"(v3),
           "f"(v4), "f"(v5), "f"(v6), "f"(v7)
        : "memory");
}

__global__ void __launch_bounds__(256)
unpool_kernel(const float4* __restrict__ x4,
              float4* __restrict__ out,
              int total)              // total = global_input_rows * 28
{
    int idx = blockIdx.x * blockDim.x + threadIdx.x;
    if (idx >= total) return;

    int irow = idx / W4_IN;           // global input row (img*112 + ih)
    int c    = idx - irow * W4_IN;    // float4 column in input row

    float4 a = __ldg(&x4[irow * W4_IN + c]);

    float4* even = out + (size_t)(2 * irow)     * W4_OUT + 2 * c;
    float4* odd  = out + (size_t)(2 * irow + 1) * W4_OUT + 2 * c;

    stg256_cs(even, a.x, 0.f, a.y, 0.f, a.z, 0.f, a.w, 0.f);
    stg256_cs(odd,  0.f, 0.f, 0.f, 0.f, 0.f, 0.f, 0.f, 0.f);
}

extern "C" void kernel_launch(void* const* d_in, const int* in_sizes, int n_in,
                              void* d_out, int out_size)
{
    const float4* x4 = (const float4*)d_in[0];
    float4* out = (float4*)d_out;

    // out_size = B*C*224*224 floats. Threads = input floats / 4 = out_size / 16.
    int total = out_size / 16;

    const int threads = 256;
    int blocks = (total + threads - 1) / threads;
    unpool_kernel<<<blocks, threads>>>(x4, out, total);
}

// round 6
// speedup vs baseline: 1.0104x; 1.0012x over previous
#include <cuda_runtime.h>
#include <cstdint>

// Unpool (stride-2 zero insertion):
//   in : (B, C, 112, 112) fp32, contiguous
//   out: (B, C, 224, 224) fp32, out[..., ::2, ::2] = in, else 0
//
// Traffic (ncu, invariant R2-R4): 455MB/replay = 411MB writes + ~44MB read
// misses (rest of the 103MB input is L2-resident across graph replays).
// This round: keep input L2-resident with ld.global.L2::evict_last —
// ptxas requires the v8/256-bit form for evict hints, so each thread loads
// 8 input floats (32B) and writes 128B:
//   even row: [x0,0,x1,0,...,x7,0] as two 256-bit .cs stores
//   odd  row: zeros, two 256-bit .cs stores
// Alignment: loads 32B-aligned (14 v8-chunks per 112-float row); even stores
// 64B-aligned (irow*1792 + c*64), odd +896 -> 32B-aligned.

namespace {
constexpr int W8_IN  = 14;   // 8-float chunks per 112-wide input row
constexpr int W4_OUT = 56;   // float4 per 224-wide output row
}

__device__ __forceinline__ void ldg256_evict_last(const void* p, float* v)
{
    asm volatile("ld.global.L2::evict_last.v8.f32 {%0,%1,%2,%3,%4,%5,%6,%7}, [%8];"
                 : "=f"(v[0]), "=f"(v[1]), "=f"(v[2]), "=f"(v[3]),
                   "=f"(v[4]), "=f"(v[5]), "=f"(v[6]), "=f"(v[7])
                 : "l"(p));
}

__device__ __forceinline__ void stg256_cs(void* p,
                                          float v0, float v1, float v2, float v3,
                                          float v4, float v5, float v6, float v7)
{
    asm volatile(
        "st.global.cs.v8.f32 [%0], {%1,%2,%3,%4,%5,%6,%7,%8};"
        :: "l"(p),
           "f"(v0), "f"(v1), "f"(v2), "f"(v3),
           "f"(v4), "f"(v5), "f"(v6), "f"(v7)
        : "memory");
}

__global__ void __launch_bounds__(256)
unpool_kernel(const float* __restrict__ x,
              float4* __restrict__ out,
              int total)              // total = global_input_rows * 14
{
    int idx = blockIdx.x * blockDim.x + threadIdx.x;
    if (idx >= total) return;

    int irow = idx / W8_IN;           // global input row (img*112 + ih)
    int c    = idx - irow * W8_IN;    // v8 column in input row

    float a[8];
    ldg256_evict_last(x + (size_t)irow * 112 + c * 8, a);

    // even output row: 16 floats = 4 float4 = 2 x v8, starting at float4 idx 4c
    float4* even = out + (size_t)(2 * irow)     * W4_OUT + 4 * c;
    float4* odd  = out + (size_t)(2 * irow + 1) * W4_OUT + 4 * c;

    stg256_cs(even,     a[0], 0.f, a[1], 0.f, a[2], 0.f, a[3], 0.f);
    stg256_cs(even + 2, a[4], 0.f, a[5], 0.f, a[6], 0.f, a[7], 0.f);
    stg256_cs(odd,      0.f, 0.f, 0.f, 0.f, 0.f, 0.f, 0.f, 0.f);
    stg256_cs(odd + 2,  0.f, 0.f, 0.f, 0.f, 0.f, 0.f, 0.f, 0.f);
}

extern "C" void kernel_launch(void* const* d_in, const int* in_sizes, int n_in,
                              void* d_out, int out_size)
{
    const float* x = (const float*)d_in[0];
    float4* out = (float4*)d_out;

    // out_size = B*C*224*224 floats. Threads = input floats / 8 = out_size / 32.
    int total = out_size / 32;

    const int threads = 256;
    int blocks = (total + threads - 1) / threads;
    unpool_kernel<<<blocks, threads>>>(x, out, total);
}